// round 16
// baseline (speedup 1.0000x reference)
#include <cuda_runtime.h>
#include <cuda_fp16.h>
#include <cstdint>

#define BB 64
#define SS 2048
#define DD 512
#define UU 512

// ---------------- scratch globals (no allocations allowed) ------------------
__device__ float g_bias[BB * UU];                  // dec@W2 + b1 + b2
__device__ float g_scores[BB * SS];                // pre-softmax scores
__device__ __half g_encH[(size_t)BB * SS * DD];    // enc as fp16 (written by kernB)
__device__ __half g_W1h[(size_t)UU * DD];          // W1 as [u][k] fp16

// ---------------- helpers ----------------------------------------------------
__device__ __forceinline__ float tanh_fast(float x) {
    float e = __expf(2.0f * x);
    return 1.0f - __fdividef(2.0f, e + 1.0f);
}
__device__ __forceinline__ uint32_t smem_u32(const void* p) {
    uint32_t a;
    asm("{ .reg .u64 t; cvta.to.shared.u64 t, %1; cvt.u32.u64 %0, t; }"
        : "=r"(a) : "l"(p));
    return a;
}
#define CP16(dst, src) \
    asm volatile("cp.async.cg.shared.global [%0], [%1], 16;" \
                 :: "r"(dst), "l"(src) : "memory")
#define STS128(addr, a, b, c, d) \
    asm volatile("st.shared.v4.b32 [%0], {%1,%2,%3,%4};" \
                 :: "r"(addr), "r"(a), "r"(b), "r"(c), "r"(d) : "memory")
#define LDSM4(r0, r1, r2, r3, addr) \
    asm volatile("ldmatrix.sync.aligned.m8n8.x4.shared.b16 {%0,%1,%2,%3}, [%4];" \
                 : "=r"(r0), "=r"(r1), "=r"(r2), "=r"(r3) : "r"(addr))
#define MMAF16(d, a0, a1, a2, a3, b0, b1) \
    asm volatile( \
        "mma.sync.aligned.m16n8k16.row.col.f32.f16.f16.f32 " \
        "{%0,%1,%2,%3}, {%4,%5,%6,%7}, {%8,%9}, {%0,%1,%2,%3};" \
        : "+f"(d[0]), "+f"(d[1]), "+f"(d[2]), "+f"(d[3]) \
        : "r"(a0), "r"(a1), "r"(a2), "r"(a3), "r"(b0), "r"(b1))

// ---------------------------------------------------------------------------
// kernWA: W1 transpose->fp16 + zero g_scores (blocks [0,1024));
// g_bias = dec@W2 + b1 + b2 (blocks [1024,1152)).
// ---------------------------------------------------------------------------
#define W_BLKS 1024
#define A_BLKS 128

__global__ __launch_bounds__(256) void kernWA(const float* __restrict__ W1,
                                              const float* __restrict__ dec,
                                              const float* __restrict__ W2,
                                              const float* __restrict__ b1,
                                              const float* __restrict__ b2) {
    int blk = blockIdx.x;
    int tid = threadIdx.x;
    if (blk < W_BLKS) {
        int idx = blk * 256 + tid;
        int u = idx & 511, kg = idx >> 9;
        g_W1h[(size_t)u * DD + kg] = __float2half_rn(W1[(size_t)kg * UU + u]);
        if (idx < BB * SS) g_scores[idx] = 0.0f;
    } else {
        __shared__ float ds[DD];
        int ab = blk - W_BLKS;
        int b = ab >> 1, half = ab & 1;
        ds[tid] = dec[b * DD + tid];
        ds[tid + 256] = dec[b * DD + tid + 256];
        __syncthreads();
        int u = half * 256 + tid;
        float acc = 0.0f;
#pragma unroll 8
        for (int k = 0; k < DD; k++) acc = fmaf(ds[k], W2[k * UU + u], acc);
        g_bias[b * UU + u] = acc + b1[u] + b2[u];
    }
}

// ---------------------------------------------------------------------------
// kernB: fp16 single-pass mma.sync GEMM, tile M64 x N256 per CTA, K=512.
// A converted fp32->fp16 IN-KERNEL (interleaved with MMA sections); CTAs with
// blockIdx.y==0 also write the fp16 image to g_encH for kernD.
// 8 k64 tiles, B via 2-stage cp.async ring, one __syncthreads/tile, 2 CTAs/SM.
// ---------------------------------------------------------------------------
#define ASLOT 9216              // 64 rows * 144 B
#define SLOT  46080             // A (9216) + B (36864)
#define EXTRA 92160             // 2 stages
#define SMEM_B_TOTAL (EXTRA + 1024 + 1024 + 1024)

__global__ __launch_bounds__(256, 2) void kernB(const float* __restrict__ enc,
                                                const float* __restrict__ Vp) {
    extern __shared__ char smraw[];
    const uint32_t smem = smem_u32(smraw);
    float* gBs = (float*)(smraw + EXTRA);
    float* Vs = (float*)(smraw + EXTRA + 1024);
    float* sPart = (float*)(smraw + EXTRA + 2048);

    const int tid = threadIdx.x;
    const int lane = tid & 31, w = tid >> 5;
    const int wm = w & 1, wn = w >> 1;          // warp tile 32(M) x 64(N)
    const int R = blockIdx.x * 64;
    const int b = blockIdx.x >> 5;
    const int s0 = (blockIdx.x & 31) * 64;
    const int N0 = blockIdx.y * 256;
    const bool wrA = (blockIdx.y == 0);

    {
        gBs[tid] = g_bias[b * 512 + N0 + tid];
        Vs[tid] = Vp[N0 + tid];
    }

    // A conversion assignment: thread t -> row r = t>>2, kq = (t&3)*16
    const int cr = tid >> 2;
    const int ckq = (tid & 3) * 16;

    // convert+store 8 fp32 -> 8 fp16 (16 B) into smem; optional gmem mirror
    auto cvt_sts8 = [&](float4 f0, float4 f1, uint32_t dst, __half* gdst) {
        __half2 p0 = __floats2half2_rn(f0.x, f0.y);
        __half2 p1 = __floats2half2_rn(f0.z, f0.w);
        __half2 p2 = __floats2half2_rn(f1.x, f1.y);
        __half2 p3 = __floats2half2_rn(f1.z, f1.w);
        uint32_t u0 = *(uint32_t*)&p0, u1 = *(uint32_t*)&p1;
        uint32_t u2 = *(uint32_t*)&p2, u3 = *(uint32_t*)&p3;
        STS128(dst, u0, u1, u2, u3);
        if (wrA) {
            uint4 v = {u0, u1, u2, u3};
            *(uint4*)gdst = v;
        }
    };

    // B tile loader (cp.async, 8 chunks/thread)
    auto issue_tileB = [&](int it, int slot) {
        const char* bSrc = (const char*)g_W1h + (size_t)N0 * 1024 + it * 128;
        uint32_t bDst = smem + slot * SLOT + ASLOT;
#pragma unroll
        for (int i = 0; i < 8; i++) {
            int lin = tid + i * 256;
            int r = lin >> 3, c = lin & 7;
            CP16(bDst + r * 144 + c * 16, bSrc + (size_t)r * 1024 + c * 16);
        }
        asm volatile("cp.async.commit_group;" ::: "memory");
    };

    float acc[2][8][4];
#pragma unroll
    for (int mt = 0; mt < 2; mt++)
#pragma unroll
        for (int nt = 0; nt < 8; nt++)
#pragma unroll
            for (int j = 0; j < 4; j++) acc[mt][nt][j] = 0.0f;

    // ---- prologue: B tile0 async; A tile0 convert into slot 0 ----
    issue_tileB(0, 0);
    {
        const float* asrc = enc + (size_t)(R + cr) * DD + ckq;
        float4 f0 = *(const float4*)(asrc);
        float4 f1 = *(const float4*)(asrc + 4);
        float4 f2 = *(const float4*)(asrc + 8);
        float4 f3 = *(const float4*)(asrc + 12);
        uint32_t d0 = smem + cr * 144 + ckq * 2;
        __half* g0 = g_encH + (size_t)(R + cr) * DD + ckq;
        cvt_sts8(f0, f1, d0, g0);
        cvt_sts8(f2, f3, d0 + 16, g0 + 8);
    }

    const uint32_t aRowOff =
        (uint32_t)((wm * 32 + (lane & 15)) * 144 + ((lane >> 4) & 1) * 16);
    const uint32_t bRowOff =
        (uint32_t)((wn * 64 + (lane & 7) + ((lane >> 4) & 1) * 8) * 144 +
                   ((lane >> 3) & 1) * 16);

    for (int it = 0; it < 8; it++) {
        asm volatile("cp.async.wait_group 0;" ::: "memory");
        __syncthreads();
        const bool more = (it + 1 < 8);
        if (more) issue_tileB(it + 1, (it + 1) & 1);

        const uint32_t sbase = smem + (it & 1) * SLOT;
        const uint32_t sA = sbase + aRowOff;
        const uint32_t sB = sbase + ASLOT + bRowOff;

        const float* asrc = enc + (size_t)(R + cr) * DD + (it + 1) * 64 + ckq;
        float4 f0, f1;
        if (more) {
            f0 = *(const float4*)(asrc);
            f1 = *(const float4*)(asrc + 4);
        }

        auto do_ks = [&](int ks) {
            uint32_t a[2][4];
#pragma unroll
            for (int mt = 0; mt < 2; mt++)
                LDSM4(a[mt][0], a[mt][1], a[mt][2], a[mt][3],
                      sA + mt * 16 * 144 + ks * 32);
            uint32_t bq[8][2];
#pragma unroll
            for (int ntp = 0; ntp < 4; ntp++)
                LDSM4(bq[ntp * 2][0], bq[ntp * 2][1],
                      bq[ntp * 2 + 1][0], bq[ntp * 2 + 1][1],
                      sB + ntp * 16 * 144 + ks * 32);
#pragma unroll
            for (int mt = 0; mt < 2; mt++)
#pragma unroll
                for (int nt = 0; nt < 8; nt++)
                    MMAF16(acc[mt][nt], a[mt][0], a[mt][1], a[mt][2],
                           a[mt][3], bq[nt][0], bq[nt][1]);
        };

        do_ks(0);
        do_ks(1);
        if (more) {
            uint32_t dA = smem + ((it + 1) & 1) * SLOT + cr * 144 + ckq * 2;
            __half* gA = g_encH + (size_t)(R + cr) * DD + (it + 1) * 64 + ckq;
            cvt_sts8(f0, f1, dA, gA);
            f0 = *(const float4*)(asrc + 8);
            f1 = *(const float4*)(asrc + 12);
        }
        do_ks(2);
        do_ks(3);
        if (more) {
            uint32_t dA = smem + ((it + 1) & 1) * SLOT + cr * 144 + ckq * 2;
            __half* gA = g_encH + (size_t)(R + cr) * DD + (it + 1) * 64 + ckq;
            cvt_sts8(f0, f1, dA + 16, gA + 8);
        }
    }

    // ---- epilogue: bias + tanh + V-dot, reduce to per-row partials ----
    __syncthreads();
    const int t4 = lane & 3;
    float part[2][2];
#pragma unroll
    for (int mt = 0; mt < 2; mt++) { part[mt][0] = 0.f; part[mt][1] = 0.f; }
#pragma unroll
    for (int mt = 0; mt < 2; mt++)
#pragma unroll
        for (int nt = 0; nt < 8; nt++) {
            int n0 = wn * 64 + nt * 8 + 2 * t4;
            float v0 = Vs[n0], v1 = Vs[n0 + 1];
            float g0 = gBs[n0], g1 = gBs[n0 + 1];
            part[mt][0] += tanh_fast(acc[mt][nt][0] + g0) * v0 +
                           tanh_fast(acc[mt][nt][1] + g1) * v1;
            part[mt][1] += tanh_fast(acc[mt][nt][2] + g0) * v0 +
                           tanh_fast(acc[mt][nt][3] + g1) * v1;
        }
#pragma unroll
    for (int mt = 0; mt < 2; mt++)
#pragma unroll
        for (int rr = 0; rr < 2; rr++) {
            part[mt][rr] += __shfl_xor_sync(0xffffffffu, part[mt][rr], 1);
            part[mt][rr] += __shfl_xor_sync(0xffffffffu, part[mt][rr], 2);
        }
    if (t4 == 0) {
        int g = lane >> 2;
#pragma unroll
        for (int mt = 0; mt < 2; mt++)
#pragma unroll
            for (int rr = 0; rr < 2; rr++) {
                int row = wm * 32 + mt * 16 + rr * 8 + g;
                sPart[row * 4 + wn] = part[mt][rr];
            }
    }
    __syncthreads();
    if (tid < 64) {
        float s = sPart[tid * 4] + sPart[tid * 4 + 1] + sPart[tid * 4 + 2] +
                  sPart[tid * 4 + 3];
        atomicAdd(&g_scores[b * SS + s0 + tid], s);
    }
}

// ---------------------------------------------------------------------------
// kernC: softmax over S; writes attn; zeroes context region
// ---------------------------------------------------------------------------
__global__ __launch_bounds__(256) void kernC(float* __restrict__ out) {
    __shared__ float red[256];
    int b = blockIdx.x, tid = threadIdx.x;
    float v[8];
    float mx = -1e30f;
#pragma unroll
    for (int j = 0; j < 8; j++) {
        v[j] = g_scores[b * SS + tid + j * 256];
        mx = fmaxf(mx, v[j]);
    }
    red[tid] = mx;
    __syncthreads();
    for (int o = 128; o > 0; o >>= 1) {
        if (tid < o) red[tid] = fmaxf(red[tid], red[tid + o]);
        __syncthreads();
    }
    mx = red[0];
    __syncthreads();
    float s = 0.0f;
#pragma unroll
    for (int j = 0; j < 8; j++) {
        v[j] = __expf(v[j] - mx);
        s += v[j];
    }
    red[tid] = s;
    __syncthreads();
    for (int o = 128; o > 0; o >>= 1) {
        if (tid < o) red[tid] += red[tid + o];
        __syncthreads();
    }
    float inv = 1.0f / red[0];
#pragma unroll
    for (int j = 0; j < 8; j++)
        out[BB * UU + b * SS + tid + j * 256] = v[j] * inv;
    for (int i = tid; i < 512; i += 256) out[b * 512 + i] = 0.0f;
}

// ---------------------------------------------------------------------------
// kernD: context[b,d] = sum_s attn[b,s] * encH[b,s,d]  (fp16 enc image)
// 8 groups of 64 threads; each thread loads uint4 (8 halves) per row ->
// 512 B/warp/LDG; smem cross-group reduction; one atomicAdd per d.
// ---------------------------------------------------------------------------
__global__ __launch_bounds__(512) void kernD(float* __restrict__ out) {
    __shared__ float as[128];
    __shared__ float red[8 * 512];
    int b = blockIdx.y, c = blockIdx.x, tid = threadIdx.x;
    if (tid < 128) as[tid] = out[BB * UU + b * SS + c * 128 + tid];
    __syncthreads();
    const int grp = tid >> 6;          // 0..7
    const int lc = tid & 63;           // 0..63
    const int d0 = lc * 8;
    const __half* e = g_encH + ((size_t)(b * SS + c * 128)) * DD + d0;
    float a0 = 0.f, a1 = 0.f, a2 = 0.f, a3 = 0.f;
    float a4 = 0.f, a5 = 0.f, a6 = 0.f, a7 = 0.f;
#pragma unroll 4
    for (int i = grp; i < 128; i += 8) {
        float wgt = as[i];
        uint4 v = *(const uint4*)(e + (size_t)i * DD);
        __half2 h0 = *(__half2*)&v.x, h1 = *(__half2*)&v.y;
        __half2 h2 = *(__half2*)&v.z, h3 = *(__half2*)&v.w;
        float2 f0 = __half22float2(h0), f1 = __half22float2(h1);
        float2 f2 = __half22float2(h2), f3 = __half22float2(h3);
        a0 = fmaf(wgt, f0.x, a0); a1 = fmaf(wgt, f0.y, a1);
        a2 = fmaf(wgt, f1.x, a2); a3 = fmaf(wgt, f1.y, a3);
        a4 = fmaf(wgt, f2.x, a4); a5 = fmaf(wgt, f2.y, a5);
        a6 = fmaf(wgt, f3.x, a6); a7 = fmaf(wgt, f3.y, a7);
    }
    float4 st0 = {a0, a1, a2, a3};
    float4 st1 = {a4, a5, a6, a7};
    *(float4*)(&red[grp * 512 + d0]) = st0;
    *(float4*)(&red[grp * 512 + d0 + 4]) = st1;
    __syncthreads();
    float s = 0.0f;
#pragma unroll
    for (int g = 0; g < 8; g++) s += red[g * 512 + tid];
    atomicAdd(&out[b * 512 + tid], s);
}

// ---------------------------------------------------------------------------
extern "C" void kernel_launch(void* const* d_in, const int* in_sizes, int n_in,
                              void* d_out, int out_size) {
    const float* enc = (const float*)d_in[0];
    const float* dec = (const float*)d_in[1];
    const float* W1  = (const float*)d_in[2];
    const float* b1  = (const float*)d_in[3];
    const float* W2  = (const float*)d_in[4];
    const float* b2  = (const float*)d_in[5];
    const float* V   = (const float*)d_in[6];
    float* out = (float*)d_out;

    cudaFuncSetAttribute(kernB, cudaFuncAttributeMaxDynamicSharedMemorySize,
                         SMEM_B_TOTAL);

    kernWA<<<W_BLKS + A_BLKS, 256>>>(W1, dec, W2, b1, b2);
    kernB<<<dim3(2048, 2), 256, SMEM_B_TOTAL>>>(enc, V);
    kernC<<<BB, 256>>>(out);
    kernD<<<dim3(16, BB), 512>>>(out);
}